// round 6
// baseline (speedup 1.0000x reference)
#include <cuda_runtime.h>

// FrequencyDecomposition: blocked 8x8 DCT -> zigzag band masks -> "inverse" that is
// actually D*Y*D^T per the reference einsum ('ik,...kl,jl->...ij').
// out[3][B][C][H][W]: band0=low, band1=mid, band2=high.
// T = D*coef*D^T (unmasked) => mid = T - low - high  (since masks partition 1).

#define STR 257  // padded shared row stride (floats): conflict-free col reads + transposed writes

__device__ __forceinline__ void dct8(const float x[8], float y[8]) {
    const float A0 = 0.35355339059327373f;
    const float C1 = 0.4903926402016152f;
    const float C2 = 0.46193976625564337f;
    const float C3 = 0.4157348061512726f;
    const float C5 = 0.2777851165098011f;
    const float C6 = 0.19134171618254492f;
    const float C7 = 0.09754516100806417f;
    float s0 = x[0] + x[7], s1 = x[1] + x[6], s2 = x[2] + x[5], s3 = x[3] + x[4];
    float d0 = x[0] - x[7], d1 = x[1] - x[6], d2 = x[2] - x[5], d3 = x[3] - x[4];
    float t0 = s0 + s3, t1 = s1 + s2, t2 = s0 - s3, t3 = s1 - s2;
    y[0] = A0 * (t0 + t1);
    y[4] = A0 * (t0 - t1);
    y[2] = C2 * t2 + C6 * t3;
    y[6] = C6 * t2 - C2 * t3;
    y[1] = C1 * d0 + C3 * d1 + C5 * d2 + C7 * d3;
    y[3] = C3 * d0 - C7 * d1 - C1 * d2 - C5 * d3;
    y[5] = C5 * d0 - C1 * d1 + C7 * d2 + C3 * d3;
    y[7] = C7 * d0 - C5 * d1 + C3 * d2 - C1 * d3;
}

__global__ __launch_bounds__(256)
void freqdec_kernel(const float* __restrict__ x, float* __restrict__ out)
{
    __shared__ float shT[8 * STR];  // holds X during fwd; then T = D*coef*D^T
    __shared__ float shW[8 * STR];  // work buffer; ends holding recHigh
    __shared__ float shL[8 * STR];  // recLow

    const int tid = threadIdx.x;
    const int b8  = tid & ~7;       // block base column (0,8,...,248)
    const int q   = tid & 7;        // lane within 8x8 block

    const int chunk  = blockIdx.x;  // 0..1  (256-col chunk)
    const int rowBlk = blockIdx.y;  // 0..63 (8-row block row)
    const int img    = blockIdx.z;  // 0..95 (B*C)

    const size_t tileOff = (size_t)img * (512 * 512)
                         + (size_t)(rowBlk * 8) * 512
                         + (size_t)chunk * 256;
    const float* src = x + tileOff;

    // ---- load 8x256 tile, float4-coalesced ----
    {
        int g = tid;
        #pragma unroll
        for (int it = 0; it < 2; ++it) {
            int r  = g >> 6;
            int c4 = (g & 63) << 2;
            float4 v4 = *reinterpret_cast<const float4*>(src + r * 512 + c4);
            float* p = &shT[r * STR + c4];
            p[0] = v4.x; p[1] = v4.y; p[2] = v4.z; p[3] = v4.w;
            g += 256;
        }
    }
    __syncthreads();

    float v[8], o[8], cf[8];

    // ---- R1: col q of X -> D*col -> write transposed: shW = (D X)^T ----
    #pragma unroll
    for (int j = 0; j < 8; ++j) v[j] = shT[j * STR + b8 + q];
    dct8(v, o);
    #pragma unroll
    for (int p = 0; p < 8; ++p) shW[q * STR + b8 + p] = o[p];
    __syncthreads();

    // ---- R2: row q of (D X) -> apply D -> cf = coef[q][*] = (D X D^T) row q ----
    #pragma unroll
    for (int j = 0; j < 8; ++j) v[j] = shW[j * STR + b8 + q];
    dct8(v, cf);
    __syncthreads();                // all shW reads done before overwrite

    // row-q band masks (zigzag: <16 low, >=48 high), bit p = column p
    const unsigned lowm  = (unsigned)((0x0000000103070F3FULL >> (q * 8)) & 0xFF);
    const unsigned highm = (unsigned)((0xFCF0E0C080000000ULL >> (q * 8)) & 0xFF);

    // ================= T = D * coef * D^T (unmasked) =================
    #pragma unroll
    for (int p = 0; p < 8; ++p) shW[q * STR + b8 + p] = cf[p];     // Y natural
    __syncthreads();
    #pragma unroll
    for (int j = 0; j < 8; ++j) v[j] = shW[j * STR + b8 + q];      // col q of Y
    dct8(v, o);
    __syncthreads();
    #pragma unroll
    for (int p = 0; p < 8; ++p) shW[q * STR + b8 + p] = o[p];      // (D Y)^T
    __syncthreads();
    #pragma unroll
    for (int j = 0; j < 8; ++j) v[j] = shW[j * STR + b8 + q];      // row q of D Y
    dct8(v, o);                                                    // o = T row q
    #pragma unroll
    for (int p = 0; p < 8; ++p) shT[q * STR + b8 + p] = o[p];      // T natural (X dead)
    __syncthreads();

    // ================= LOW band =================
    #pragma unroll
    for (int p = 0; p < 8; ++p)
        shW[q * STR + b8 + p] = ((lowm >> p) & 1) ? cf[p] : 0.0f;
    __syncthreads();
    #pragma unroll
    for (int j = 0; j < 8; ++j) v[j] = shW[j * STR + b8 + q];
    dct8(v, o);
    __syncthreads();
    #pragma unroll
    for (int p = 0; p < 8; ++p) shW[q * STR + b8 + p] = o[p];
    __syncthreads();
    #pragma unroll
    for (int j = 0; j < 8; ++j) v[j] = shW[j * STR + b8 + q];
    dct8(v, o);                                                    // recLow row q
    #pragma unroll
    for (int p = 0; p < 8; ++p) shL[q * STR + b8 + p] = o[p];
    __syncthreads();

    // ================= HIGH band =================
    #pragma unroll
    for (int p = 0; p < 8; ++p)
        shW[q * STR + b8 + p] = ((highm >> p) & 1) ? cf[p] : 0.0f;
    __syncthreads();
    #pragma unroll
    for (int j = 0; j < 8; ++j) v[j] = shW[j * STR + b8 + q];
    dct8(v, o);
    __syncthreads();
    #pragma unroll
    for (int p = 0; p < 8; ++p) shW[q * STR + b8 + p] = o[p];
    __syncthreads();
    #pragma unroll
    for (int j = 0; j < 8; ++j) v[j] = shW[j * STR + b8 + q];
    dct8(v, o);                                                    // recHigh row q
    __syncthreads();                // all reads done before natural overwrite
    #pragma unroll
    for (int p = 0; p < 8; ++p) shW[q * STR + b8 + p] = o[p];
    __syncthreads();

    // ---- store: low, mid = T - low - high, high. Warp-contiguous 128B stores ----
    const size_t N = (size_t)32 * 3 * 512 * 512;  // 25165824
    float* oL = out + tileOff;
    float* oM = out + N + tileOff;
    float* oH = out + 2 * N + tileOff;
    #pragma unroll
    for (int r = 0; r < 8; ++r) {
        float tv = shT[r * STR + tid];
        float lv = shL[r * STR + tid];
        float hv = shW[r * STR + tid];
        size_t go = (size_t)r * 512 + tid;
        oL[go] = lv;
        oM[go] = tv - lv - hv;
        oH[go] = hv;
    }
}

extern "C" void kernel_launch(void* const* d_in, const int* in_sizes, int n_in,
                              void* d_out, int out_size)
{
    const float* x = (const float*)d_in[0];
    float* out = (float*)d_out;
    (void)in_sizes; (void)n_in; (void)out_size;

    dim3 grid(2, 64, 96);   // (W/256, H/8, B*C)
    dim3 block(256);
    freqdec_kernel<<<grid, block>>>(x, out);
}

// round 8
// speedup vs baseline: 1.8530x; 1.8530x over previous
#include <cuda_runtime.h>

// FrequencyDecomposition: blocked 8x8 DCT -> zigzag band masks -> D*Y*D^T per band.
// out[3][B][C][H][W]: band0=low, band1=mid, band2=high (mid via its own mask).
// All-register formulation: one thread = one full 8x8 block. No shared memory,
// no barriers; both transform directions are thread-local.
// (R7 resubmission of R6 kernel — prior bench failure was a container flake.)

__device__ __forceinline__ void dct8(const float x[8], float y[8]) {
    const float A0 = 0.35355339059327373f;
    const float C1 = 0.4903926402016152f;
    const float C2 = 0.46193976625564337f;
    const float C3 = 0.4157348061512726f;
    const float C5 = 0.2777851165098011f;
    const float C6 = 0.19134171618254492f;
    const float C7 = 0.09754516100806417f;
    float s0 = x[0] + x[7], s1 = x[1] + x[6], s2 = x[2] + x[5], s3 = x[3] + x[4];
    float d0 = x[0] - x[7], d1 = x[1] - x[6], d2 = x[2] - x[5], d3 = x[3] - x[4];
    float t0 = s0 + s3, t1 = s1 + s2, t2 = s0 - s3, t3 = s1 - s2;
    y[0] = A0 * (t0 + t1);
    y[4] = A0 * (t0 - t1);
    y[2] = C2 * t2 + C6 * t3;
    y[6] = C6 * t2 - C2 * t3;
    y[1] = C1 * d0 + C3 * d1 + C5 * d2 + C7 * d3;
    y[3] = C3 * d0 - C7 * d1 - C1 * d2 - C5 * d3;
    y[5] = C5 * d0 - C1 * d1 + C7 * d2 + C3 * d3;
    y[7] = C7 * d0 - C5 * d1 + C3 * d2 - C1 * d3;
}

// rec = D * (MASK o cf) * D^T, stored to dst (row stride 512).
// MASK bit (r*8+p) = keep cf[r][p]. Compile-time mask -> zeros fold into butterflies.
template<unsigned long long MASK>
__device__ __forceinline__ void band_store(const float cf[64], float* __restrict__ dst) {
    float Z[64];
    // row transform of masked coef: Z = Y * D^T
    #pragma unroll
    for (int r = 0; r < 8; ++r) {
        float in[8];
        #pragma unroll
        for (int p = 0; p < 8; ++p)
            in[p] = ((MASK >> (r * 8 + p)) & 1ULL) ? cf[r * 8 + p] : 0.0f;
        dct8(in, &Z[r * 8]);
    }
    // column transform in place: rec = D * Z
    #pragma unroll
    for (int j = 0; j < 8; ++j) {
        float in[8], o[8];
        #pragma unroll
        for (int i = 0; i < 8; ++i) in[i] = Z[i * 8 + j];
        dct8(in, o);
        #pragma unroll
        for (int i = 0; i < 8; ++i) Z[i * 8 + j] = o[i];
    }
    // store 8 rows as 2x float4
    #pragma unroll
    for (int r = 0; r < 8; ++r) {
        float4 a = make_float4(Z[r*8+0], Z[r*8+1], Z[r*8+2], Z[r*8+3]);
        float4 b = make_float4(Z[r*8+4], Z[r*8+5], Z[r*8+6], Z[r*8+7]);
        *reinterpret_cast<float4*>(dst + (size_t)r * 512)     = a;
        *reinterpret_cast<float4*>(dst + (size_t)r * 512 + 4) = b;
    }
}

__global__ __launch_bounds__(128, 3)
void freqdec_kernel(const float* __restrict__ x, float* __restrict__ out)
{
    const int tid = threadIdx.x;
    const int cb  = tid & 63;              // block-col 0..63  (lane-contiguous)
    const int rp  = tid >> 6;              // 0..1
    const int rb  = blockIdx.x * 2 + rp;   // block-row 0..63
    const int img = blockIdx.y;            // 0..95 (B*C)

    const size_t base = (size_t)img * (512 * 512)
                      + (size_t)rb * 8 * 512
                      + (size_t)cb * 8;
    const float* src = x + base;

    // ---- load full 8x8 block into registers (16 independent LDG.128) ----
    float X[64];
    #pragma unroll
    for (int r = 0; r < 8; ++r) {
        float4 a = *reinterpret_cast<const float4*>(src + (size_t)r * 512);
        float4 b = *reinterpret_cast<const float4*>(src + (size_t)r * 512 + 4);
        X[r*8+0] = a.x; X[r*8+1] = a.y; X[r*8+2] = a.z; X[r*8+3] = a.w;
        X[r*8+4] = b.x; X[r*8+5] = b.y; X[r*8+6] = b.z; X[r*8+7] = b.w;
    }

    // ---- forward: cf = D * X * D^T (col dct, then row dct, in place) ----
    #pragma unroll
    for (int j = 0; j < 8; ++j) {
        float in[8], o[8];
        #pragma unroll
        for (int i = 0; i < 8; ++i) in[i] = X[i * 8 + j];
        dct8(in, o);
        #pragma unroll
        for (int i = 0; i < 8; ++i) X[i * 8 + j] = o[i];
    }
    #pragma unroll
    for (int r = 0; r < 8; ++r) {
        float in[8];
        #pragma unroll
        for (int i = 0; i < 8; ++i) in[i] = X[r * 8 + i];
        dct8(in, &X[r * 8]);
    }

    // ---- three masked reconstructions, stored directly ----
    const size_t N = (size_t)32 * 3 * 512 * 512;  // 25165824
    band_store<0x0000000103070F3FULL>(X, out + base);           // low  (zigzag < 16)
    band_store<0x030F1F3E7CF8F0C0ULL>(X, out + N + base);       // mid
    band_store<0xFCF0E0C080000000ULL>(X, out + 2 * N + base);   // high (zigzag >= 48)
}

extern "C" void kernel_launch(void* const* d_in, const int* in_sizes, int n_in,
                              void* d_out, int out_size)
{
    const float* x = (const float*)d_in[0];
    float* out = (float*)d_out;
    (void)in_sizes; (void)n_in; (void)out_size;

    dim3 grid(32, 96);   // (64 block-rows / 2 per CTA, B*C)
    freqdec_kernel<<<grid, 128>>>(x, out);
}

// round 9
// speedup vs baseline: 2.5720x; 1.3880x over previous
#include <cuda_runtime.h>

// FrequencyDecomposition: blocked 8x8 DCT -> zigzag band masks -> D*Y*D^T per band.
// out[3][B][C][H][W]: band0=low, band1=mid, band2=high.
// Lane-pair formulation: 2 threads per 8x8 block, each owns 4 columns (32 floats).
// Column transforms are thread-local; row transforms exchange half-rows with
// shfl.xor(1). All global loads/stores are fully coalesced (contiguous 16B/lane).

__device__ __forceinline__ void dct8(const float x[8], float y[8]) {
    const float A0 = 0.35355339059327373f;
    const float C1 = 0.4903926402016152f;
    const float C2 = 0.46193976625564337f;
    const float C3 = 0.4157348061512726f;
    const float C5 = 0.2777851165098011f;
    const float C6 = 0.19134171618254492f;
    const float C7 = 0.09754516100806417f;
    float s0 = x[0] + x[7], s1 = x[1] + x[6], s2 = x[2] + x[5], s3 = x[3] + x[4];
    float d0 = x[0] - x[7], d1 = x[1] - x[6], d2 = x[2] - x[5], d3 = x[3] - x[4];
    float t0 = s0 + s3, t1 = s1 + s2, t2 = s0 - s3, t3 = s1 - s2;
    y[0] = A0 * (t0 + t1);
    y[4] = A0 * (t0 - t1);
    y[2] = C2 * t2 + C6 * t3;
    y[6] = C6 * t2 - C2 * t3;
    y[1] = C1 * d0 + C3 * d1 + C5 * d2 + C7 * d3;
    y[3] = C3 * d0 - C7 * d1 - C1 * d2 - C5 * d3;
    y[5] = C5 * d0 - C1 * d1 + C7 * d2 + C3 * d3;
    y[7] = C7 * d0 - C5 * d1 + C3 * d2 - C1 * d3;
}

// Row-transform stage: Z = rowDCT(MASK o cf). cf/Z hold this thread's 4 columns
// (global cols h*4..h*4+3) of 8 rows. Half-rows exchanged with the pair lane.
// Rows whose full 8-bit mask is zero are skipped at compile time.
template<unsigned long long MASK>
__device__ __forceinline__ void band_rows(const float cf[32], float Z[32], int h) {
    #pragma unroll
    for (int i = 0; i < 8; ++i) {
        const unsigned rowm = (unsigned)((MASK >> (i * 8)) & 0xFF);
        if (rowm == 0u) {
            #pragma unroll
            for (int p = 0; p < 4; ++p) Z[i * 4 + p] = 0.0f;
        } else {
            float own[4], oth[4];
            #pragma unroll
            for (int p = 0; p < 4; ++p) {
                own[p] = cf[i * 4 + p];
                oth[p] = __shfl_xor_sync(0xFFFFFFFFu, own[p], 1);
            }
            float x[8];
            #pragma unroll
            for (int p = 0; p < 4; ++p) {
                float lo = h ? oth[p] : own[p];   // global cols 0..3
                float hi = h ? own[p] : oth[p];   // global cols 4..7
                x[p]     = ((rowm >> p) & 1u)       ? lo : 0.0f;  // compile-time mask
                x[4 + p] = ((rowm >> (4 + p)) & 1u) ? hi : 0.0f;
            }
            float y[8];
            dct8(x, y);
            #pragma unroll
            for (int p = 0; p < 4; ++p) Z[i * 4 + p] = h ? y[4 + p] : y[p];
        }
    }
}

// Column transform (thread-local) on Z in place, then 8 coalesced float4 stores.
__device__ __forceinline__ void band_cols_store(float Z[32], float* __restrict__ dst) {
    #pragma unroll
    for (int c = 0; c < 4; ++c) {
        float in[8], o[8];
        #pragma unroll
        for (int i = 0; i < 8; ++i) in[i] = Z[i * 4 + c];
        dct8(in, o);
        #pragma unroll
        for (int i = 0; i < 8; ++i) Z[i * 4 + c] = o[i];
    }
    #pragma unroll
    for (int r = 0; r < 8; ++r) {
        float4 v = make_float4(Z[r*4+0], Z[r*4+1], Z[r*4+2], Z[r*4+3]);
        *reinterpret_cast<float4*>(dst + (size_t)r * 512) = v;
    }
}

__global__ __launch_bounds__(128, 5)
void freqdec_kernel(const float* __restrict__ x, float* __restrict__ out)
{
    const int tid = threadIdx.x;
    const int h   = tid & 1;           // half: 0 -> cols 0..3, 1 -> cols 4..7
    const int b   = tid >> 1;          // block-col 0..63
    const int rb  = blockIdx.x;        // block-row 0..63
    const int img = blockIdx.y;        // 0..95 (B*C)

    const size_t base = (size_t)img * (512 * 512)
                      + (size_t)rb * 8 * 512
                      + (size_t)b * 8 + (size_t)h * 4;
    const float* src = x + base;

    // ---- load: 8 coalesced LDG.128 (lane l covers byte l*16 of a 512B span) ----
    float X[32];
    #pragma unroll
    for (int r = 0; r < 8; ++r) {
        float4 v = *reinterpret_cast<const float4*>(src + (size_t)r * 512);
        X[r*4+0] = v.x; X[r*4+1] = v.y; X[r*4+2] = v.z; X[r*4+3] = v.w;
    }

    // ---- forward col DCT (local): X <- D * X ----
    #pragma unroll
    for (int c = 0; c < 4; ++c) {
        float in[8], o[8];
        #pragma unroll
        for (int i = 0; i < 8; ++i) in[i] = X[i * 4 + c];
        dct8(in, o);
        #pragma unroll
        for (int i = 0; i < 8; ++i) X[i * 4 + c] = o[i];
    }
    // ---- forward row DCT (shfl): X <- cf = (D X) * D^T ----
    band_rows<0xFFFFFFFFFFFFFFFFULL>(X, X, h);

    // ---- three masked reconstructions ----
    const size_t N = (size_t)32 * 3 * 512 * 512;  // 25165824
    float Z[32];
    band_rows<0x0000000103070F3FULL>(X, Z, h);      // low  (zigzag < 16)
    band_cols_store(Z, out + base);
    band_rows<0x030F1F3E7CF8F0C0ULL>(X, Z, h);      // mid
    band_cols_store(Z, out + N + base);
    band_rows<0xFCF0E0C080000000ULL>(X, Z, h);      // high (zigzag >= 48)
    band_cols_store(Z, out + 2 * N + base);
}

extern "C" void kernel_launch(void* const* d_in, const int* in_sizes, int n_in,
                              void* d_out, int out_size)
{
    const float* x = (const float*)d_in[0];
    float* out = (float*)d_out;
    (void)in_sizes; (void)n_in; (void)out_size;

    dim3 grid(64, 96);   // (block-rows, B*C); 128 threads = 64 blocks * 2 lanes
    freqdec_kernel<<<grid, 128>>>(x, out);
}